// round 10
// baseline (speedup 1.0000x reference)
#include <cuda_runtime.h>
#include <cuda_bf16.h>

// AngularSymmetryMod: out[b,i,p] = 0.125 * sum_{j,k} (1 + lambda_p*cos(theta_ijk - th_p))^4
//                                   * exp(-1.12*((Rij+Rik)/2 - Rs_p)^2) * f_ij * f_ik
// p = lambda_idx*20 + Rs_idx*4 + theta_idx  (np.meshgrid 'xy' flatten)
// One block per (b,i); j<=k triangular pairs, weight 2 off-diagonal.
// cos computed literally as cosf(fl32(theta - th)) to bit-match reference rounding.
//
// R4/R7: TPB 128/256 both ~12.8us, issue 46.6->56.9%, no pipe >16% => total-inst bound.
// R9: redux.sync.add.f32 does NOT exist on sm_103 (ptxas). This round:
//   - main loop: packed f32x2 (mul/fma.rn.f32x2) for the (lambda=+1,-1) channel pair
//   - epilogue: smem transpose-reduce instead of 40x(5 SHFL + 5 FADD) butterfly:
//     all threads store partials to red[40][TPB], then 8 warps each own 5 outputs.

#define TPB 256
#define NWARP (TPB / 32)
#define NATOM 32
#define NPAIR (NATOM * (NATOM + 1) / 2)   // 528

typedef unsigned long long u64;

__device__ __forceinline__ u64 pack2(float lo, float hi) {
    u64 r; asm("mov.b64 %0, {%1, %2};" : "=l"(r) : "f"(lo), "f"(hi)); return r;
}
__device__ __forceinline__ void unpack2(u64 v, float& lo, float& hi) {
    asm("mov.b64 {%0, %1}, %2;" : "=f"(lo), "=f"(hi) : "l"(v));
}
__device__ __forceinline__ u64 mul2(u64 a, u64 b) {
    u64 r; asm("mul.rn.f32x2 %0, %1, %2;" : "=l"(r) : "l"(a), "l"(b)); return r;
}
__device__ __forceinline__ u64 fma2(u64 a, u64 b, u64 c) {
    u64 r; asm("fma.rn.f32x2 %0, %1, %2, %3;" : "=l"(r) : "l"(a), "l"(b), "l"(c)); return r;
}

__global__ __launch_bounds__(TPB)
void angsym_kernel(const float* __restrict__ dcut,
                   const float* __restrict__ dmat,
                   const float* __restrict__ coords,
                   float* __restrict__ out)
{
    const int bi = blockIdx.x;             // 0..511
    const int b = bi >> 5;
    const int i = bi & 31;

    __shared__ float vx[NATOM], vy[NATOM], vz[NATOM], Rr[NATOM], Ff[NATOM];
    __shared__ float red[40][TPB];         // 40 KB transpose-reduce staging

    const int t = threadIdx.x;

    const float cix = coords[(b * NATOM + i) * 3 + 0];
    const float ciy = coords[(b * NATOM + i) * 3 + 1];
    const float ciz = coords[(b * NATOM + i) * 3 + 2];

    if (t < NATOM) {
        const int j = t;
        vx[j] = cix - coords[(b * NATOM + j) * 3 + 0];
        vy[j] = ciy - coords[(b * NATOM + j) * 3 + 1];
        vz[j] = ciz - coords[(b * NATOM + j) * 3 + 2];
        Rr[j] = dmat[(b * NATOM + i) * NATOM + j];
        Ff[j] = dcut[(b * NATOM + i) * NATOM + j];
    }
    __syncthreads();

    // Rs = {0.5,1.17,1.83,2.5,3.17}/BOHR  (double-evaluated, rounds like np f64->f32)
    const float Rs[5] = {
        (float)(0.5  / 0.52917721092),
        (float)(1.17 / 0.52917721092),
        (float)(1.83 / 0.52917721092),
        (float)(2.5  / 0.52917721092),
        (float)(3.17 / 0.52917721092)
    };
    const float TH[4] = { 0.0f, 1.57f, 3.14f, 4.71f };

    // acc2[r*4+tt] packs (lambda=+1 -> out idx r*4+tt, lambda=-1 -> out idx 20+r*4+tt)
    u64 acc2[20];
#pragma unroll
    for (int p = 0; p < 20; ++p) acc2[p] = 0ull;

    for (int p = t; p < NPAIR; p += TPB) {
        // decode triangular pair index: p = k*(k+1)/2 + j, j <= k.
        // 8p+1 <= 4217 exact in fp32; sqrtf correctly rounded -> k within 1.
        int k = (int)((sqrtf(8.0f * (float)p + 1.0f) - 1.0f) * 0.5f);
        if ((k + 1) * (k + 2) / 2 <= p) ++k;
        if (k * (k + 1) / 2 > p) --k;
        const int j = p - k * (k + 1) / 2;

        const float Rj = Rr[j], Rk = Rr[k];
        const float dot = vx[j] * vx[k] + vy[j] * vy[k] + vz[j] * vz[k];
        const float theta = dot / (Rj * Rk + 1e-5f);

        const float avg = 0.5f * (Rj + Rk);
        const float w = Ff[j] * Ff[k] * ((j != k) ? 2.0f : 1.0f);

        u64 rad2[5];
#pragma unroll
        for (int r = 0; r < 5; ++r) {
            const float u = avg - Rs[r];
            const float rv = __expf(-1.12f * u * u) * w;
            rad2[r] = pack2(rv, rv);
        }

#pragma unroll
        for (int tt = 0; tt < 4; ++tt) {
            // accurate cosf of the fp32-rounded (theta - th): bit-matches reference arg
            const float ca = cosf(theta - TH[tt]);
            const u64 pa = pack2(1.0f + ca, 1.0f - ca);   // (1+c, 1-c)
            const u64 p2 = mul2(pa, pa);
            const u64 p4 = mul2(p2, p2);                  // ((1+c)^4, (1-c)^4)
#pragma unroll
            for (int r = 0; r < 5; ++r) {
                acc2[r * 4 + tt] = fma2(p4, rad2[r], acc2[r * 4 + tt]);
            }
        }
    }

    __syncthreads();   // reuse red[] only after all warps passed the input-stage use

    // transpose: every thread deposits its 40 partials at column t
#pragma unroll
    for (int p = 0; p < 20; ++p) {
        float lo, hi;
        unpack2(acc2[p], lo, hi);
        red[p][t]      = lo;
        red[20 + p][t] = hi;
    }
    __syncthreads();

    // 8 warps x 5 outputs: warp w owns outputs p = 5w .. 5w+4
    const int warp = t >> 5, lane = t & 31;
#pragma unroll
    for (int q = 0; q < 5; ++q) {
        const int p = warp * 5 + q;
        float v = 0.0f;
#pragma unroll
        for (int m = 0; m < TPB / 32; ++m) v += red[p][lane + 32 * m];
        v += __shfl_down_sync(0xffffffffu, v, 16);
        v += __shfl_down_sync(0xffffffffu, v, 8);
        v += __shfl_down_sync(0xffffffffu, v, 4);
        v += __shfl_down_sync(0xffffffffu, v, 2);
        v += __shfl_down_sync(0xffffffffu, v, 1);
        if (lane == 0) out[bi * 40 + p] = 0.125f * v;   // 2^{1-zeta} = 0.125
    }
}

extern "C" void kernel_launch(void* const* d_in, const int* in_sizes, int n_in,
                              void* d_out, int out_size)
{
    const float* dcut   = (const float*)d_in[0];  // d_cutoff (16,32,32)
    const float* dmat   = (const float*)d_in[1];  // d        (16,32,32)
    const float* coords = (const float*)d_in[2];  // atom_coordinates (16,32,3)
    float* out = (float*)d_out;                   // (16,32,40)
    (void)in_sizes; (void)n_in; (void)out_size;

    angsym_kernel<<<512, TPB>>>(dcut, dmat, coords, out);
}

// round 11
// speedup vs baseline: 1.1834x; 1.1834x over previous
#include <cuda_runtime.h>
#include <cuda_bf16.h>

// AngularSymmetryMod: out[b,i,p] = 0.125 * sum_{j,k} (1 + lambda_p*cos(theta_ijk - th_p))^4
//                                   * exp(-1.12*((Rij+Rik)/2 - Rs_p)^2) * f_ij * f_ik
// p = lambda*20 + Rs*4 + th (np.meshgrid 'xy'). One block per (b,i); j<=k pairs, wt 2 off-diag.
// cos literal: cosf(fl32(theta - th)) bit-matches reference rounding at large theta.
//
// R10 evidence: regs=64 -> ~15 scratch regs -> zero ILP, 13 cyc/issue/warp. R11:
//  - launch_bounds(128,4): 128 regs, still 4 CTA/SM, full grid resident
//  - dual-pair ILP batches (528 = 4*128 + 16)
//  - radial factorization: 5 expf/pair -> 1 expf/pair + per-atom tables (exact algebra)
//  - smem (j,k) table kills the sqrt decode chain

#define TPB 128
#define NATOM 32
#define NPAIR (NATOM * (NATOM + 1) / 2)   // 528

typedef unsigned long long u64;

__device__ __forceinline__ u64 pack2(float lo, float hi) {
    u64 r; asm("mov.b64 %0, {%1, %2};" : "=l"(r) : "f"(lo), "f"(hi)); return r;
}
__device__ __forceinline__ void unpack2(u64 v, float& lo, float& hi) {
    asm("mov.b64 {%0, %1}, %2;" : "=f"(lo), "=f"(hi) : "l"(v));
}
__device__ __forceinline__ u64 mul2(u64 a, u64 b) {
    u64 r; asm("mul.rn.f32x2 %0, %1, %2;" : "=l"(r) : "l"(a), "l"(b)); return r;
}
__device__ __forceinline__ u64 fma2(u64 a, u64 b, u64 c) {
    u64 r; asm("fma.rn.f32x2 %0, %1, %2, %3;" : "=l"(r) : "l"(a), "l"(b), "l"(c)); return r;
}

__global__ __launch_bounds__(TPB, 4)
void angsym_kernel(const float* __restrict__ dcut,
                   const float* __restrict__ dmat,
                   const float* __restrict__ coords,
                   float* __restrict__ out)
{
    const int bi = blockIdx.x;             // 0..511
    const int b = bi >> 5;
    const int i = bi & 31;

    __shared__ float4 atomv[NATOM];            // (vx, vy, vz, R)
    __shared__ float  Fsh[NATOM];
    __shared__ float  Ash[NATOM][5];           // exp(-0.28 R^2 + 1.12 Rs_r R)
    __shared__ float  Bsh[NATOM][5];           // Ash * exp(-1.12 Rs_r^2)
    __shared__ unsigned short jk[NPAIR];
    __shared__ float  red[40][TPB];            // 20 KB transpose-reduce

    const int t = threadIdx.x;

    // Rs = {0.5,1.17,1.83,2.5,3.17}/BOHR (double-evaluated -> same f32 as numpy)
    const float Rs[5] = {
        (float)(0.5  / 0.52917721092),
        (float)(1.17 / 0.52917721092),
        (float)(1.83 / 0.52917721092),
        (float)(2.5  / 0.52917721092),
        (float)(3.17 / 0.52917721092)
    };
    const float TH[4] = { 0.0f, 1.57f, 3.14f, 4.71f };

    const float cix = coords[(b * NATOM + i) * 3 + 0];
    const float ciy = coords[(b * NATOM + i) * 3 + 1];
    const float ciz = coords[(b * NATOM + i) * 3 + 2];

    if (t < NATOM) {
        const int j = t;
        const float R = dmat[(b * NATOM + i) * NATOM + j];
        atomv[j] = make_float4(cix - coords[(b * NATOM + j) * 3 + 0],
                               ciy - coords[(b * NATOM + j) * 3 + 1],
                               ciz - coords[(b * NATOM + j) * 3 + 2],
                               R);
        Fsh[j] = dcut[(b * NATOM + i) * NATOM + j];
#pragma unroll
        for (int r = 0; r < 5; ++r) {
            const float a = __expf(fmaf(1.12f * Rs[r], R, -0.28f * R * R));
            Ash[j][r] = a;
            Bsh[j][r] = a * __expf(-1.12f * Rs[r] * Rs[r]);
        }
        // triangular index table: row k holds pairs (j<=k)
        const int base = j * (j + 1) / 2;
        for (int jj = 0; jj <= j; ++jj)
            jk[base + jj] = (unsigned short)(jj | (j << 8));
    }
    __syncthreads();

    // acc2[r*4+tt] packs (lambda=+1 -> out r*4+tt, lambda=-1 -> out 20+r*4+tt)
    u64 acc2[20];
#pragma unroll
    for (int p = 0; p < 20; ++p) acc2[p] = 0ull;

    auto do_pair = [&](int p) {
        const unsigned int e = jk[p];
        const int j = e & 31;
        const int k = e >> 8;
        const float4 aj = atomv[j];
        const float4 ak = atomv[k];
        const float dot = aj.x * ak.x + aj.y * ak.y + aj.z * ak.z;
        const float RR  = aj.w * ak.w;
        const float theta = dot / (RR + 1e-5f);          // IEEE div, bit-safe
        const float w  = Fsh[j] * Fsh[k] * ((j != k) ? 2.0f : 1.0f);
        const float Xw = __expf(-0.56f * RR) * w;        // single exp per pair

        u64 rad2[5];
#pragma unroll
        for (int r = 0; r < 5; ++r) {
            const float rv = Ash[j][r] * Bsh[k][r] * Xw;
            rad2[r] = pack2(rv, rv);
        }
#pragma unroll
        for (int tt = 0; tt < 4; ++tt) {
            const float ca = cosf(theta - TH[tt]);       // literal, matches ref rounding
            const u64 pa = pack2(1.0f + ca, 1.0f - ca);
            const u64 p2 = mul2(pa, pa);
            const u64 p4 = mul2(p2, p2);                 // ((1+c)^4, (1-c)^4)
#pragma unroll
            for (int r = 0; r < 5; ++r)
                acc2[r * 4 + tt] = fma2(p4, rad2[r], acc2[r * 4 + tt]);
        }
    };

    // 528 pairs = 2 dual-batches (4*128) + 16 remainder; dual pairs are independent -> ILP
#pragma unroll
    for (int batch = 0; batch < 2; ++batch) {
        do_pair(t + batch * 256);
        do_pair(t + batch * 256 + 128);
    }
    if (t < 16) do_pair(512 + t);

    __syncthreads();
#pragma unroll
    for (int p = 0; p < 20; ++p) {
        float lo, hi;
        unpack2(acc2[p], lo, hi);
        red[p][t]      = lo;
        red[20 + p][t] = hi;
    }
    __syncthreads();

    // 4 warps x 10 outputs each
    const int warp = t >> 5, lane = t & 31;
#pragma unroll
    for (int q = 0; q < 10; ++q) {
        const int p = warp * 10 + q;
        float v = red[p][lane] + red[p][lane + 32] + red[p][lane + 64] + red[p][lane + 96];
        v += __shfl_down_sync(0xffffffffu, v, 16);
        v += __shfl_down_sync(0xffffffffu, v, 8);
        v += __shfl_down_sync(0xffffffffu, v, 4);
        v += __shfl_down_sync(0xffffffffu, v, 2);
        v += __shfl_down_sync(0xffffffffu, v, 1);
        if (lane == 0) out[bi * 40 + p] = 0.125f * v;    // 2^{1-zeta} = 0.125
    }
}

extern "C" void kernel_launch(void* const* d_in, const int* in_sizes, int n_in,
                              void* d_out, int out_size)
{
    const float* dcut   = (const float*)d_in[0];  // d_cutoff (16,32,32)
    const float* dmat   = (const float*)d_in[1];  // d        (16,32,32)
    const float* coords = (const float*)d_in[2];  // atom_coordinates (16,32,3)
    float* out = (float*)d_out;                   // (16,32,40)
    (void)in_sizes; (void)n_in; (void)out_size;

    angsym_kernel<<<512, TPB>>>(dcut, dmat, coords, out);
}